// round 6
// baseline (speedup 1.0000x reference)
#include <cuda_runtime.h>
#include <cstdint>

// Problem dims
#define Bb   4
#define Ss   512
#define Dd   1024
#define Hh   16
#define HDh  64
#define KR   64
#define Mrows (Bb*Ss)          // 2048
#define THREE_D (3*Dd)         // 3072

__device__ __constant__ float kSCALE = 0.125f;   // 1/sqrt(64)
#define ALPHA_F 0.25f

// Scratch (device globals; no allocation allowed)
__device__ float g_qkv[3*Bb*Hh*Ss*HDh];   // [t][b*H+h][s][hd]
__device__ float g_ks [Bb*Hh*Ss*HDh];     // smoothed K
__device__ float g_vs [Bb*Hh*Ss*HDh];     // smoothed V
__device__ float g_attnout[Bb*Ss*Dd];     // [b][s][h*64+hd] == [B*S, D]

// ---------------------------------------------------------------------------
// Tiled fp32 SGEMM: C[M,N] = A[M,K] @ B[K,N] + bias[N]
// BM=BN=128, BK=16, TM=TN=8, 256 threads.
// QKV_SCATTER: scatter epilogue into g_qkv [t][bh][s][hd] layout.
// A_FROM_ATTN: read A from g_attnout (device global) instead of the A arg.
// ---------------------------------------------------------------------------
template<bool QKV_SCATTER, bool A_FROM_ATTN>
__global__ __launch_bounds__(256) void sgemm_k(
    int M, int N, int Kd,
    const float* __restrict__ Ain, const float* __restrict__ Bm,
    const float* __restrict__ bias, float* __restrict__ C)
{
    __shared__ float As[16][128];
    __shared__ float Bs[16][128];

    const int tid = threadIdx.x;
    const int cCol = blockIdx.x;   // N tile
    const int cRow = blockIdx.y;   // M tile

    const float* A = (A_FROM_ATTN ? (const float*)g_attnout : Ain) + (size_t)cRow*128*Kd;
    const float* Bp = Bm + cCol*128;

    const int innerRowA = tid >> 2;        // 0..63
    const int innerColA = tid & 3;         // float4 within 16-wide K slab
    const int innerRowB = tid >> 5;        // 0..7
    const int innerColB = tid & 31;        // float4 col

    const int threadCol = tid & 15;        // 0..15
    const int threadRow = tid >> 4;        // 0..15

    float acc[8][8];
    #pragma unroll
    for (int i = 0; i < 8; i++)
        #pragma unroll
        for (int j = 0; j < 8; j++) acc[i][j] = 0.f;

    for (int kt = 0; kt < Kd; kt += 16) {
        // A tile 128x16 -> As transposed [k][m]
        #pragma unroll
        for (int off = 0; off < 128; off += 64) {
            float4 t4 = *(const float4*)(&A[(size_t)(innerRowA+off)*Kd + kt + innerColA*4]);
            As[innerColA*4+0][innerRowA+off] = t4.x;
            As[innerColA*4+1][innerRowA+off] = t4.y;
            As[innerColA*4+2][innerRowA+off] = t4.z;
            As[innerColA*4+3][innerRowA+off] = t4.w;
        }
        // B tile 16x128
        #pragma unroll
        for (int off = 0; off < 16; off += 8) {
            *(float4*)(&Bs[innerRowB+off][innerColB*4]) =
                *(const float4*)(&Bp[(size_t)(kt+innerRowB+off)*N + innerColB*4]);
        }
        __syncthreads();

        #pragma unroll
        for (int dot = 0; dot < 16; ++dot) {
            float4 m0 = *(const float4*)(&As[dot][threadRow*8]);
            float4 m1 = *(const float4*)(&As[dot][threadRow*8+4]);
            float4 n0 = *(const float4*)(&Bs[dot][threadCol*8]);
            float4 n1 = *(const float4*)(&Bs[dot][threadCol*8+4]);
            float rm[8] = {m0.x,m0.y,m0.z,m0.w,m1.x,m1.y,m1.z,m1.w};
            float rn[8] = {n0.x,n0.y,n0.z,n0.w,n1.x,n1.y,n1.z,n1.w};
            #pragma unroll
            for (int i = 0; i < 8; i++)
                #pragma unroll
                for (int j = 0; j < 8; j++)
                    acc[i][j] += rm[i]*rn[j];
        }
        __syncthreads();
    }

    #pragma unroll
    for (int i = 0; i < 8; i++) {
        const int m = cRow*128 + threadRow*8 + i;
        #pragma unroll
        for (int j = 0; j < 8; j++) {
            const int n = cCol*128 + threadCol*8 + j;
            const float val = acc[i][j] + bias[n];
            if (QKV_SCATTER) {
                const int t  = n >> 10;          // 0..2
                const int h  = (n >> 6) & 15;
                const int hd = n & 63;
                const int b  = m >> 9;           // /S
                const int s  = m & 511;
                const int bh = b*Hh + h;
                g_qkv[(((size_t)t*Bb*Hh + bh)*Ss + s)*HDh + hd] = val;
            } else {
                C[(size_t)m*N + n] = val;
            }
        }
    }
}

// ---------------------------------------------------------------------------
// Neighbor smoothing: k_s[j] = (1-a)k[j] + a/2 (k[clip(j-1)] + k[clip(j+1)])
// one thread per float4 (16 per head-row), k and v in the same pass
// ---------------------------------------------------------------------------
__global__ __launch_bounds__(256) void smooth_kernel()
{
    const int idx = blockIdx.x*blockDim.x + threadIdx.x;   // over B*H*S*16
    const int total = Bb*Hh*Ss*16;
    if (idx >= total) return;
    const int f  = idx & 15;
    const int s  = (idx >> 4) & (Ss-1);
    const int bh = idx >> 13;                               // /(16*512)

    const float4* qkv4 = (const float4*)g_qkv;
    const float w0 = 1.0f - ALPHA_F;
    const float w1 = ALPHA_F * 0.5f;
    const int dl = (s > 0)    ? -16 : 0;
    const int dr = (s < Ss-1) ?  16 : 0;

    // K (t=1)
    {
        const int base = (((Bb*Hh) + bh)*Ss + s)*16 + f;
        float4 c = qkv4[base], l = qkv4[base+dl], r = qkv4[base+dr];
        float4 o;
        o.x = w0*c.x + w1*(l.x + r.x);
        o.y = w0*c.y + w1*(l.y + r.y);
        o.z = w0*c.z + w1*(l.z + r.z);
        o.w = w0*c.w + w1*(l.w + r.w);
        ((float4*)g_ks)[(bh*Ss + s)*16 + f] = o;
    }
    // V (t=2)
    {
        const int base = (((2*Bb*Hh) + bh)*Ss + s)*16 + f;
        float4 c = qkv4[base], l = qkv4[base+dl], r = qkv4[base+dr];
        float4 o;
        o.x = w0*c.x + w1*(l.x + r.x);
        o.y = w0*c.y + w1*(l.y + r.y);
        o.z = w0*c.z + w1*(l.z + r.z);
        o.w = w0*c.w + w1*(l.w + r.w);
        ((float4*)g_vs)[(bh*Ss + s)*16 + f] = o;
    }
}

// ---------------------------------------------------------------------------
// Routed attention: one warp per query (b,h,s).
// Phase 1: each lane owns routes {lane, lane+32}; full 64-dim dot per route
//          with q broadcast from SMEM (no warp reductions for scores).
// Softmax: two warp reductions (max, sum).
// Phase 2: each lane owns output dims {2*lane, 2*lane+1}; coalesced V reads,
//          attn weights broadcast from SMEM.
// ---------------------------------------------------------------------------
__global__ __launch_bounds__(256) void attn_kernel(const int* __restrict__ routes)
{
    __shared__ float qs    [8][64];
    __shared__ float attn_s[8][64];
    __shared__ int   rt_s  [8][64];

    const int warp = threadIdx.x >> 5;
    const int lane = threadIdx.x & 31;
    const int gq = blockIdx.x*8 + warp;      // (b*H + h)*S + s
    const int s  = gq & (Ss-1);
    const int bh = gq >> 9;

    const float* qrow = g_qkv + ((size_t)bh*Ss + s)*HDh;   // t=0
    const float* kb   = g_ks + (size_t)bh*Ss*HDh;
    const float* vb   = g_vs + (size_t)bh*Ss*HDh;

    if (lane < 16)
        ((float4*)qs[warp])[lane] = ((const float4*)qrow)[lane];
    const int r0 = routes[s*KR + lane];
    const int r1 = routes[s*KR + 32 + lane];
    rt_s[warp][lane]      = r0;
    rt_s[warp][lane + 32] = r1;
    __syncwarp();

    // Phase 1: scores
    const float4* k0 = (const float4*)(kb + r0*HDh);
    const float4* k1 = (const float4*)(kb + r1*HDh);
    const float4* q4 = (const float4*)qs[warp];
    float a0 = 0.f, a1 = 0.f;
    #pragma unroll
    for (int d = 0; d < 16; ++d) {
        float4 qv = q4[d];
        float4 x0 = k0[d];
        float4 x1 = k1[d];
        a0 += qv.x*x0.x + qv.y*x0.y + qv.z*x0.z + qv.w*x0.w;
        a1 += qv.x*x1.x + qv.y*x1.y + qv.z*x1.z + qv.w*x1.w;
    }
    float sc0 = (r0 > s) ? -1e9f : a0 * kSCALE;
    float sc1 = (r1 > s) ? -1e9f : a1 * kSCALE;

    // softmax across warp
    float mx = fmaxf(sc0, sc1);
    #pragma unroll
    for (int o = 16; o > 0; o >>= 1)
        mx = fmaxf(mx, __shfl_xor_sync(0xffffffffu, mx, o));
    float e0 = __expf(sc0 - mx);
    float e1 = __expf(sc1 - mx);
    float sum = e0 + e1;
    #pragma unroll
    for (int o = 16; o > 0; o >>= 1)
        sum += __shfl_xor_sync(0xffffffffu, sum, o);
    const float inv = 1.0f / sum;
    attn_s[warp][lane]      = e0 * inv;
    attn_s[warp][lane + 32] = e1 * inv;
    __syncwarp();

    // Phase 2: output (lane owns dims 2*lane, 2*lane+1)
    float o0 = 0.f, o1 = 0.f;
    #pragma unroll 8
    for (int j = 0; j < KR; ++j) {
        const int   rj = rt_s[warp][j];
        const float w  = attn_s[warp][j];
        const float2 vv = *(const float2*)(vb + rj*HDh + 2*lane);
        o0 += w*vv.x;
        o1 += w*vv.y;
    }

    const int b = bh >> 4;
    const int h = bh & 15;
    float2* op = (float2*)(g_attnout + ((size_t)(b*Ss + s))*Dd + h*HDh) + lane;
    *op = make_float2(o0, o1);
}

// ---------------------------------------------------------------------------
extern "C" void kernel_launch(void* const* d_in, const int* in_sizes, int n_in,
                              void* d_out, int out_size)
{
    const float* x      = (const float*)d_in[0];   // [B,S,D]
    const float* w_qkv  = (const float*)d_in[1];   // [D, 3D]
    const float* b_qkv  = (const float*)d_in[2];   // [3D]
    const float* w_out  = (const float*)d_in[3];   // [D, D]
    const float* b_out  = (const float*)d_in[4];   // [D]
    const int*   routes = (const int*)d_in[5];     // [S, K]
    float* out = (float*)d_out;                    // [B,S,D]

    // 1) QKV projection + scatter into [t][bh][s][hd]
    {
        dim3 grid(THREE_D/128, Mrows/128);         // (24, 16)
        sgemm_k<true, false><<<grid, 256>>>(Mrows, THREE_D, Dd, x, w_qkv, b_qkv, nullptr);
    }
    // 2) neighbor smoothing of K/V
    {
        const int total = Bb*Hh*Ss*16;
        smooth_kernel<<<(total + 255)/256, 256>>>();
    }
    // 3) routed attention -> g_attnout [B*S, D]
    {
        attn_kernel<<<(Bb*Hh*Ss)/8, 256>>>(routes);
    }
    // 4) output projection
    {
        dim3 grid(Dd/128, Mrows/128);              // (8, 16)
        sgemm_k<false, true><<<grid, 256>>>(Mrows, Dd, Dd, nullptr, w_out, b_out, out);
    }
}